// round 11
// baseline (speedup 1.0000x reference)
#include <cuda_runtime.h>
#include <cuda_fp16.h>
#include <cstdint>
#include <math.h>

#define B_SZ 64
#define N_SZ 512
#define H_SZ 512
#define NQ 8
#define NLAYERS 4

#define KCHUNK 64
#define TILE_A 16384                    // 128 rows x 128B
#define TILE_B 32768                    // 256 rows x 128B
#define STAGE_BYTES (TILE_A + TILE_B)   // 48KB
#define NSTAGE 3
#define SMEM_GEMM (NSTAGE * STAGE_BYTES)   // 144KB
#define NTHREADS 256

// ---------------------------------------------------------------------------
// Static scratch (no allocs allowed)
// ---------------------------------------------------------------------------
__device__ __half g_xT[(size_t)B_SZ * H_SZ * N_SZ];   // rounded fp16
__device__ __half g_adj[N_SZ * N_SZ];                 // rounded fp16
__device__ __half g_W[H_SZ * H_SZ];                   // rounded fp16
__device__ __half g_g1[(size_t)B_SZ * N_SZ * H_SZ];   // fp16

// ---------------------------------------------------------------------------
// helpers
// ---------------------------------------------------------------------------
__device__ __forceinline__ uint32_t smem_u32(const void* p) {
    uint32_t a;
    asm("{ .reg .u64 t; cvta.to.shared.u64 t, %1; cvt.u32.u64 %0, t; }" : "=r"(a) : "l"(p));
    return a;
}
// SW128 swizzle (bits[6:4] ^= bits[9:7]) — for 128B rows
__device__ __forceinline__ uint32_t swz(uint32_t o) { return o ^ ((o >> 3) & 0x70); }

__device__ __forceinline__ void cp16(uint32_t dst, const void* src) {
    asm volatile("cp.async.cg.shared.global [%0], [%1], 16;" :: "r"(dst), "l"(src));
}
__device__ __forceinline__ void ldsm4(uint32_t* r, uint32_t addr) {
    asm volatile("ldmatrix.sync.aligned.m8n8.x4.shared.b16 {%0,%1,%2,%3}, [%4];"
                 : "=r"(r[0]), "=r"(r[1]), "=r"(r[2]), "=r"(r[3]) : "r"(addr));
}
__device__ __forceinline__ void mma_f16(float* c, const uint32_t* a, const uint32_t* b) {
    asm volatile(
        "mma.sync.aligned.m16n8k16.row.col.f32.f16.f16.f32 "
        "{%0,%1,%2,%3}, {%4,%5,%6,%7}, {%8,%9}, {%0,%1,%2,%3};"
        : "+f"(c[0]), "+f"(c[1]), "+f"(c[2]), "+f"(c[3])
        : "r"(a[0]), "r"(a[1]), "r"(a[2]), "r"(a[3]), "r"(b[0]), "r"(b[1]));
}

// ---------------------------------------------------------------------------
// Conversion kernels
// ---------------------------------------------------------------------------
// x[b,j,h] fp32 -> xT[b,h,j] fp16 ; 32x32 tile transpose
__global__ void conv_xT_kernel(const float* __restrict__ x) {
    __shared__ float tile[32][33];
    const int b = blockIdx.z;
    const int j0 = blockIdx.y * 32;
    const int h0 = blockIdx.x * 32;
    const int tid = threadIdx.x;
    const int ty = tid >> 5, tx = tid & 31;
    const float* X = x + (size_t)b * N_SZ * H_SZ;
#pragma unroll
    for (int r = 0; r < 4; r++)
        tile[ty + r * 8][tx] = X[(size_t)(j0 + ty + r * 8) * H_SZ + h0 + tx];
    __syncthreads();
    __half* o = g_xT + (size_t)b * H_SZ * N_SZ;
#pragma unroll
    for (int r = 0; r < 4; r++) {
        const int hrow = h0 + ty + r * 8;
        o[(size_t)hrow * N_SZ + j0 + tx] = __float2half(tile[tx][ty + r * 8]);
    }
}

// adj and W -> single fp16 planes
__global__ void conv_small_kernel(const float* __restrict__ adj,
                                  const float* __restrict__ W) {
    int base = blockIdx.x * 1024 + threadIdx.x;
    const float* src = (blockIdx.y == 0) ? adj : W;
    __half* dst = (blockIdx.y == 0) ? g_adj : g_W;
#pragma unroll
    for (int i = 0; i < 4; i++) {
        int idx = base + i * 256;
        dst[idx] = __float2half(src[idx]);
    }
}

// ---------------------------------------------------------------------------
// GEMM plumbing.  CTA tile 128(M)x256(N), 8 warps (2x4), warp tile 64x64.
// Single-term fp16: C = A*B.
// ---------------------------------------------------------------------------
// prefetch 128x64 A-chunk and 256x64 B-chunk (row stride 512) into a stage
__device__ __forceinline__ void prefetch_chunk(
    uint32_t sb, int stage, int kc, int tid,
    const __half* __restrict__ A, const __half* __restrict__ B) {
    const uint32_t base = sb + stage * STAGE_BYTES;
    const __half* As = A + kc * KCHUNK;
    const __half* Bs = B + kc * KCHUNK;
#pragma unroll
    for (int i = 0; i < 4; i++) {          // A: 1024 16B-chunks
        const int j = tid + i * NTHREADS;
        const int row = j >> 3, c = j & 7;
        cp16(base + swz(row * 128 + c * 16), As + (size_t)row * 512 + c * 8);
    }
#pragma unroll
    for (int i = 0; i < 8; i++) {          // B: 2048 16B-chunks
        const int j = tid + i * NTHREADS;
        const int row = j >> 3, c = j & 7;
        cp16(base + TILE_A + swz(row * 128 + c * 16), Bs + (size_t)row * 512 + c * 8);
    }
    asm volatile("cp.async.commit_group;");
}

// fp16 MMA over one 128x256x64 chunk. Warp computes 64x64.
__device__ __forceinline__ void compute_chunk(uint32_t sb, int stage, int wid, int lane,
                                              float acc[4][8][4]) {
    const uint32_t base = sb + stage * STAGE_BYTES;
    const int m0 = (wid & 1) * 64;
    const int n0 = (wid >> 1) * 64;
    const int ar = (lane & 7) + ((lane >> 3) & 1) * 8;
    const int ac = ((lane >> 4) & 1) * 8;
    const int br = (lane & 7) + ((lane >> 4) & 1) * 8;
    const int bc = ((lane >> 3) & 1) * 8;
#pragma unroll
    for (int ks = 0; ks < 4; ks++) {
        uint32_t a[4][4], b[8][2];
#pragma unroll
        for (int mt = 0; mt < 4; mt++) {
            const uint32_t off = swz((m0 + mt * 16 + ar) * 128 + (ks * 16 + ac) * 2);
            ldsm4(a[mt], base + off);
        }
#pragma unroll
        for (int nt2 = 0; nt2 < 4; nt2++) {
            const uint32_t off = swz((n0 + nt2 * 16 + br) * 128 + (ks * 16 + bc) * 2);
            uint32_t r[4];
            ldsm4(r, base + TILE_A + off);
            b[nt2 * 2][0] = r[0]; b[nt2 * 2][1] = r[1];
            b[nt2 * 2 + 1][0] = r[2]; b[nt2 * 2 + 1][1] = r[3];
        }
#pragma unroll
        for (int mt = 0; mt < 4; mt++)
#pragma unroll
            for (int nt = 0; nt < 8; nt++)
                mma_f16(acc[mt][nt], a[mt], b[nt]);
    }
}

// 8 chunks of K=64, 3-stage pipeline, ONE barrier per iteration.
__device__ __forceinline__ void gemm_mainloop(
    uint32_t sb, int tid, int wid, int lane, float acc[4][8][4],
    const __half* A, const __half* B) {
    prefetch_chunk(sb, 0, 0, tid, A, B);
    prefetch_chunk(sb, 1, 1, tid, A, B);
#pragma unroll 1
    for (int kc = 0; kc < 8; kc++) {
        if (kc == 7) asm volatile("cp.async.wait_group 0;");
        else         asm volatile("cp.async.wait_group 1;");
        __syncthreads();
        if (kc + 2 < 8)
            prefetch_chunk(sb, (kc + 2) % NSTAGE, kc + 2, tid, A, B);
        compute_chunk(sb, kc % NSTAGE, wid, lane, acc);
    }
}

// ---------------------------------------------------------------------------
// GEMM1: g1[b,i,h] = sum_j adj[i,j]*x[b,j,h] -> fp16. grid (2,4,64)
// ---------------------------------------------------------------------------
__global__ __launch_bounds__(NTHREADS, 1) void gemm1_mma_kernel() {
    extern __shared__ __align__(128) char smem[];
    const uint32_t sb = smem_u32(smem);
    const int tid = threadIdx.x, wid = tid >> 5, lane = tid & 31;
    const int b = blockIdx.z;
    const int iBase = blockIdx.y * 128;
    const int hBase = blockIdx.x * 256;

    float acc[4][8][4];
#pragma unroll
    for (int i = 0; i < 4; i++)
#pragma unroll
        for (int j = 0; j < 8; j++)
#pragma unroll
            for (int k = 0; k < 4; k++) acc[i][j][k] = 0.f;

    gemm_mainloop(sb, tid, wid, lane, acc,
                  g_adj + (size_t)iBase * 512,
                  g_xT + ((size_t)b * 512 + hBase) * 512);

    const int m0 = (wid & 1) * 64, n0 = (wid >> 1) * 64;
    const int g = lane >> 2, t = lane & 3;
#pragma unroll
    for (int mt = 0; mt < 4; mt++)
#pragma unroll
        for (int nt = 0; nt < 8; nt++) {
            const int r0 = iBase + m0 + mt * 16 + g;
            const int col = hBase + n0 + nt * 8 + t * 2;
            const size_t o0 = ((size_t)b * 512 + r0) * 512 + col;
            const size_t o1 = o0 + (size_t)8 * 512;
            __half2 v0, v1;
            v0.x = __float2half(acc[mt][nt][0]);
            v0.y = __float2half(acc[mt][nt][1]);
            v1.x = __float2half(acc[mt][nt][2]);
            v1.y = __float2half(acc[mt][nt][3]);
            *(__half2*)(g_g1 + o0) = v0;
            *(__half2*)(g_g1 + o1) = v1;
        }
}

// ---------------------------------------------------------------------------
// GEMM2 + bias + exact GELU.  grid (2, 256)
// ---------------------------------------------------------------------------
__device__ __forceinline__ float gelu_exact(float v) {
    return 0.5f * v * (1.0f + erff(v * 0.70710678118654752440f));
}

__global__ __launch_bounds__(NTHREADS, 1) void gemm2_mma_kernel(const float* __restrict__ bias,
                                                                float* __restrict__ out) {
    extern __shared__ __align__(128) char smem[];
    const uint32_t sb = smem_u32(smem);
    const int tid = threadIdx.x, wid = tid >> 5, lane = tid & 31;
    const int mBase = blockIdx.y * 128;
    const int nBase = blockIdx.x * 256;

    float acc[4][8][4];
#pragma unroll
    for (int i = 0; i < 4; i++)
#pragma unroll
        for (int j = 0; j < 8; j++)
#pragma unroll
            for (int k = 0; k < 4; k++) acc[i][j][k] = 0.f;

    gemm_mainloop(sb, tid, wid, lane, acc,
                  g_g1 + (size_t)mBase * 512,
                  g_W + (size_t)nBase * 512);

    const int m0 = (wid & 1) * 64, n0 = (wid >> 1) * 64;
    const int g = lane >> 2, t = lane & 3;
#pragma unroll
    for (int mt = 0; mt < 4; mt++)
#pragma unroll
        for (int nt = 0; nt < 8; nt++) {
            const int r0 = mBase + m0 + mt * 16 + g;
            const int col = nBase + n0 + nt * 8 + t * 2;
            const float b0 = __ldg(bias + col), b1 = __ldg(bias + col + 1);
            float2 v0, v1;
            v0.x = gelu_exact(acc[mt][nt][0] + b0);
            v0.y = gelu_exact(acc[mt][nt][1] + b1);
            v1.x = gelu_exact(acc[mt][nt][2] + b0);
            v1.y = gelu_exact(acc[mt][nt][3] + b1);
            *(float2*)(out + (size_t)r0 * 512 + col) = v0;
            *(float2*)(out + (size_t)(r0 + 8) * 512 + col) = v1;
        }
}

// ---------------------------------------------------------------------------
// Quantum circuit + pre/post projections (one block per batch element)
// ---------------------------------------------------------------------------
__global__ void quantum_kernel(const float* __restrict__ pre_w,
                               const float* __restrict__ pre_b,
                               const float* __restrict__ post_w,
                               const float* __restrict__ post_b,
                               const float* __restrict__ qw,
                               float* __restrict__ out) {
    const int b = blockIdx.x;
    const int tid = threadIdx.x;
    const int warp = tid >> 5;
    const int lane = tid & 31;

    __shared__ float angles[NQ];
    __shared__ float sre[256], sim_[256];
    __shared__ float probs[256];
    __shared__ float zs[NQ];

    const float* tgt = out + (size_t)b * N_SZ * H_SZ;

    {
        float partial = 0.f;
        const float* pw = pre_w + warp * H_SZ;
        for (int k = lane; k < H_SZ; k += 32) partial += tgt[k] * pw[k];
#pragma unroll
        for (int o = 16; o; o >>= 1) partial += __shfl_down_sync(0xffffffffu, partial, o);
        if (lane == 0)
            angles[warp] = tanhf(partial + pre_b[warp]) * 3.14159265358979323846f;
    }

    sre[tid] = (tid == 0) ? 1.f : 0.f;
    sim_[tid] = 0.f;
    __syncthreads();

    for (int w = 0; w < NQ; w++) {
        const int mask = 1 << (7 - w);
        const float th = angles[w] * 0.5f;
        const float c = cosf(th), s = sinf(th);
        if (tid < 128) {
            const int i0 = ((tid & ~(mask - 1)) << 1) | (tid & (mask - 1));
            const int i1 = i0 | mask;
            float a0r = sre[i0], a0i = sim_[i0];
            float a1r = sre[i1], a1i = sim_[i1];
            sre[i0] = c * a0r - s * a1r;
            sim_[i0] = c * a0i - s * a1i;
            sre[i1] = s * a0r + c * a1r;
            sim_[i1] = s * a0i + c * a1i;
        }
        __syncthreads();
    }

    for (int l = 0; l < NLAYERS; l++) {
        for (int w = 0; w < NQ; w++) {
            const int mask = 1 << (7 - w);
            const float th = qw[l * NQ + w] * 0.5f;
            const float c = cosf(th), s = sinf(th);
            if (tid < 128) {
                const int i0 = ((tid & ~(mask - 1)) << 1) | (tid & (mask - 1));
                const int i1 = i0 | mask;
                float a0r = sre[i0], a0i = sim_[i0];
                float a1r = sre[i1], a1i = sim_[i1];
                sre[i0] = c * a0r + s * a1i;
                sim_[i0] = c * a0i - s * a1r;
                sre[i1] = c * a1r + s * a0i;
                sim_[i1] = c * a1i - s * a0r;
            }
            __syncthreads();
        }
        for (int w = 0; w < NQ; w++) {
            const int t = (w + 1) & 7;
            const int mc = 1 << (7 - w);
            const int mt = 1 << (7 - t);
            const int src = (tid & mc) ? (tid ^ mt) : tid;
            const float vr = sre[src], vi = sim_[src];
            __syncthreads();
            sre[tid] = vr;
            sim_[tid] = vi;
            __syncthreads();
        }
    }

    probs[tid] = sre[tid] * sre[tid] + sim_[tid] * sim_[tid];
    __syncthreads();
    {
        const int m = 1 << (7 - warp);
        float z = 0.f;
        for (int i = lane; i < 256; i += 32)
            z += (i & m) ? -probs[i] : probs[i];
#pragma unroll
        for (int o = 16; o; o >>= 1) z += __shfl_down_sync(0xffffffffu, z, o);
        if (lane == 0) zs[warp] = z;
    }
    __syncthreads();

    for (int h = tid; h < H_SZ; h += 256) {
        float acc = post_b[h];
#pragma unroll
        for (int q = 0; q < NQ; q++) acc += zs[q] * post_w[h * NQ + q];
        out[(size_t)b * N_SZ * H_SZ + h] = acc;
    }
}

// ---------------------------------------------------------------------------
extern "C" void kernel_launch(void* const* d_in, const int* in_sizes, int n_in,
                              void* d_out, int out_size) {
    const float* x      = (const float*)d_in[0];
    const float* adj    = (const float*)d_in[1];
    const float* Wg     = (const float*)d_in[2];
    const float* bg     = (const float*)d_in[3];
    const float* pre_w  = (const float*)d_in[4];
    const float* pre_b  = (const float*)d_in[5];
    const float* post_w = (const float*)d_in[6];
    const float* post_b = (const float*)d_in[7];
    const float* qw     = (const float*)d_in[8];
    float* out = (float*)d_out;

    cudaFuncSetAttribute(gemm1_mma_kernel,
                         cudaFuncAttributeMaxDynamicSharedMemorySize, SMEM_GEMM);
    cudaFuncSetAttribute(gemm2_mma_kernel,
                         cudaFuncAttributeMaxDynamicSharedMemorySize, SMEM_GEMM);

    conv_xT_kernel<<<dim3(16, 16, 64), 256>>>(x);
    conv_small_kernel<<<dim3(256, 2), 256>>>(adj, Wg);
    gemm1_mma_kernel<<<dim3(2, 4, 64), NTHREADS, SMEM_GEMM>>>();
    gemm2_mma_kernel<<<dim3(2, 256), NTHREADS, SMEM_GEMM>>>(bg, out);
    quantum_kernel<<<B_SZ, 256>>>(pre_w, pre_b, post_w, post_b, qw, out);
}

// round 14
// speedup vs baseline: 1.4671x; 1.4671x over previous
#include <cuda_runtime.h>
#include <cuda_fp16.h>
#include <cstdint>
#include <math.h>

#define B_SZ 64
#define N_SZ 512
#define H_SZ 512
#define NQ 8
#define NLAYERS 4

#define KCHUNK 64
#define TILE_A 16384                    // 128 rows x 128B
#define TILE_B 32768                    // 256 rows x 128B
#define STAGE_BYTES (TILE_A + TILE_B)   // 48KB
#define NSTAGE 4
#define SMEM_GEMM (NSTAGE * STAGE_BYTES)   // 192KB
#define NTHREADS 256

// ---------------------------------------------------------------------------
// Static scratch (no allocs allowed)
// ---------------------------------------------------------------------------
__device__ __half g_xT[(size_t)B_SZ * H_SZ * N_SZ];   // rounded fp16
__device__ __half g_adj[N_SZ * N_SZ];                 // rounded fp16
__device__ __half g_W[H_SZ * H_SZ];                   // rounded fp16
__device__ __half g_g1[(size_t)B_SZ * N_SZ * H_SZ];   // fp16

// ---------------------------------------------------------------------------
// helpers
// ---------------------------------------------------------------------------
__device__ __forceinline__ uint32_t smem_u32(const void* p) {
    uint32_t a;
    asm("{ .reg .u64 t; cvta.to.shared.u64 t, %1; cvt.u32.u64 %0, t; }" : "=r"(a) : "l"(p));
    return a;
}
// SW128 swizzle (bits[6:4] ^= bits[9:7]) — for 128B rows
__device__ __forceinline__ uint32_t swz(uint32_t o) { return o ^ ((o >> 3) & 0x70); }

__device__ __forceinline__ void cp16(uint32_t dst, const void* src) {
    asm volatile("cp.async.cg.shared.global [%0], [%1], 16;" :: "r"(dst), "l"(src));
}
__device__ __forceinline__ void ldsm4(uint32_t* r, uint32_t addr) {
    asm volatile("ldmatrix.sync.aligned.m8n8.x4.shared.b16 {%0,%1,%2,%3}, [%4];"
                 : "=r"(r[0]), "=r"(r[1]), "=r"(r[2]), "=r"(r[3]) : "r"(addr));
}
__device__ __forceinline__ void mma_f16(float* c, const uint32_t* a, const uint32_t* b) {
    asm volatile(
        "mma.sync.aligned.m16n8k16.row.col.f32.f16.f16.f32 "
        "{%0,%1,%2,%3}, {%4,%5,%6,%7}, {%8,%9}, {%0,%1,%2,%3};"
        : "+f"(c[0]), "+f"(c[1]), "+f"(c[2]), "+f"(c[3])
        : "r"(a[0]), "r"(a[1]), "r"(a[2]), "r"(a[3]), "r"(b[0]), "r"(b[1]));
}

// ---------------------------------------------------------------------------
// Conversion kernels
// ---------------------------------------------------------------------------
// x[b,j,h] fp32 -> xT[b,h,j] fp16 ; 32x32 tile transpose
__global__ void conv_xT_kernel(const float* __restrict__ x) {
    __shared__ float tile[32][33];
    const int b = blockIdx.z;
    const int j0 = blockIdx.y * 32;
    const int h0 = blockIdx.x * 32;
    const int tid = threadIdx.x;
    const int ty = tid >> 5, tx = tid & 31;
    const float* X = x + (size_t)b * N_SZ * H_SZ;
#pragma unroll
    for (int r = 0; r < 4; r++)
        tile[ty + r * 8][tx] = X[(size_t)(j0 + ty + r * 8) * H_SZ + h0 + tx];
    __syncthreads();
    __half* o = g_xT + (size_t)b * H_SZ * N_SZ;
#pragma unroll
    for (int r = 0; r < 4; r++) {
        const int hrow = h0 + ty + r * 8;
        o[(size_t)hrow * N_SZ + j0 + tx] = __float2half(tile[tx][ty + r * 8]);
    }
}

// adj and W -> single fp16 planes
__global__ void conv_small_kernel(const float* __restrict__ adj,
                                  const float* __restrict__ W) {
    int base = blockIdx.x * 1024 + threadIdx.x;
    const float* src = (blockIdx.y == 0) ? adj : W;
    __half* dst = (blockIdx.y == 0) ? g_adj : g_W;
#pragma unroll
    for (int i = 0; i < 4; i++) {
        int idx = base + i * 256;
        dst[idx] = __float2half(src[idx]);
    }
}

// ---------------------------------------------------------------------------
// GEMM plumbing.  CTA tile 128(M)x256(N), 8 warps (2x4), warp tile 64x64.
// Single-term fp16: C = A*B.  A-frags streamed to keep registers low.
// ---------------------------------------------------------------------------
// prefetch 128x64 A-chunk and 256x64 B-chunk (row stride 512) into a stage
__device__ __forceinline__ void prefetch_chunk(
    uint32_t sb, int stage, int kc, int tid,
    const __half* __restrict__ A, const __half* __restrict__ B) {
    const uint32_t base = sb + stage * STAGE_BYTES;
    const __half* As = A + kc * KCHUNK;
    const __half* Bs = B + kc * KCHUNK;
#pragma unroll
    for (int i = 0; i < 4; i++) {          // A: 1024 16B-chunks
        const int j = tid + i * NTHREADS;
        const int row = j >> 3, c = j & 7;
        cp16(base + swz(row * 128 + c * 16), As + (size_t)row * 512 + c * 8);
    }
#pragma unroll
    for (int i = 0; i < 8; i++) {          // B: 2048 16B-chunks
        const int j = tid + i * NTHREADS;
        const int row = j >> 3, c = j & 7;
        cp16(base + TILE_A + swz(row * 128 + c * 16), Bs + (size_t)row * 512 + c * 8);
    }
    asm volatile("cp.async.commit_group;");
}

// fp16 MMA over one 128x256x64 chunk. Warp computes 64x64.
// B frags (16 regs) held per ks; A frag (4 regs) streamed per m-tile.
__device__ __forceinline__ void compute_chunk(uint32_t sb, int stage, int wid, int lane,
                                              float acc[4][8][4]) {
    const uint32_t base = sb + stage * STAGE_BYTES;
    const int m0 = (wid & 1) * 64;
    const int n0 = (wid >> 1) * 64;
    const int ar = (lane & 7) + ((lane >> 3) & 1) * 8;
    const int ac = ((lane >> 4) & 1) * 8;
    const int br = (lane & 7) + ((lane >> 4) & 1) * 8;
    const int bc = ((lane >> 3) & 1) * 8;
#pragma unroll
    for (int ks = 0; ks < 4; ks++) {
        uint32_t b[8][2];
#pragma unroll
        for (int nt2 = 0; nt2 < 4; nt2++) {
            const uint32_t off = swz((n0 + nt2 * 16 + br) * 128 + (ks * 16 + bc) * 2);
            uint32_t r[4];
            ldsm4(r, base + TILE_A + off);
            b[nt2 * 2][0] = r[0]; b[nt2 * 2][1] = r[1];
            b[nt2 * 2 + 1][0] = r[2]; b[nt2 * 2 + 1][1] = r[3];
        }
#pragma unroll
        for (int mt = 0; mt < 4; mt++) {
            uint32_t a[4];
            const uint32_t off = swz((m0 + mt * 16 + ar) * 128 + (ks * 16 + ac) * 2);
            ldsm4(a, base + off);
#pragma unroll
            for (int nt = 0; nt < 8; nt++)
                mma_f16(acc[mt][nt], a, b[nt]);
        }
    }
}

// 8 chunks of K=64, 4-stage pipeline, ONE barrier per iteration.
// Prefetch at iter kc targets stage (kc+3)%4 == stage computed at kc-1,
// which this iteration's barrier fences.
__device__ __forceinline__ void gemm_mainloop(
    uint32_t sb, int tid, int wid, int lane, float acc[4][8][4],
    const __half* A, const __half* B) {
    prefetch_chunk(sb, 0, 0, tid, A, B);
    prefetch_chunk(sb, 1, 1, tid, A, B);
    prefetch_chunk(sb, 2, 2, tid, A, B);
#pragma unroll 1
    for (int kc = 0; kc < 8; kc++) {
        if (kc < 6)       asm volatile("cp.async.wait_group 2;");
        else if (kc == 6) asm volatile("cp.async.wait_group 1;");
        else              asm volatile("cp.async.wait_group 0;");
        __syncthreads();
        if (kc + 3 < 8)
            prefetch_chunk(sb, (kc + 3) & 3, kc + 3, tid, A, B);
        compute_chunk(sb, kc & 3, wid, lane, acc);
    }
}

// ---------------------------------------------------------------------------
// GEMM1: g1[b,i,h] = sum_j adj[i,j]*x[b,j,h] -> fp16. grid (2,4,64)
// ---------------------------------------------------------------------------
__global__ __launch_bounds__(NTHREADS, 1) void gemm1_mma_kernel() {
    extern __shared__ __align__(128) char smem[];
    const uint32_t sb = smem_u32(smem);
    const int tid = threadIdx.x, wid = tid >> 5, lane = tid & 31;
    const int b = blockIdx.z;
    const int iBase = blockIdx.y * 128;
    const int hBase = blockIdx.x * 256;

    float acc[4][8][4];
#pragma unroll
    for (int i = 0; i < 4; i++)
#pragma unroll
        for (int j = 0; j < 8; j++)
#pragma unroll
            for (int k = 0; k < 4; k++) acc[i][j][k] = 0.f;

    gemm_mainloop(sb, tid, wid, lane, acc,
                  g_adj + (size_t)iBase * 512,
                  g_xT + ((size_t)b * 512 + hBase) * 512);

    const int m0 = (wid & 1) * 64, n0 = (wid >> 1) * 64;
    const int g = lane >> 2, t = lane & 3;
#pragma unroll
    for (int mt = 0; mt < 4; mt++)
#pragma unroll
        for (int nt = 0; nt < 8; nt++) {
            const int r0 = iBase + m0 + mt * 16 + g;
            const int col = hBase + n0 + nt * 8 + t * 2;
            const size_t o0 = ((size_t)b * 512 + r0) * 512 + col;
            const size_t o1 = o0 + (size_t)8 * 512;
            __half2 v0, v1;
            v0.x = __float2half(acc[mt][nt][0]);
            v0.y = __float2half(acc[mt][nt][1]);
            v1.x = __float2half(acc[mt][nt][2]);
            v1.y = __float2half(acc[mt][nt][3]);
            *(__half2*)(g_g1 + o0) = v0;
            *(__half2*)(g_g1 + o1) = v1;
        }
}

// ---------------------------------------------------------------------------
// GEMM2 + bias + exact GELU.  grid (2, 256)
// ---------------------------------------------------------------------------
__device__ __forceinline__ float gelu_exact(float v) {
    return 0.5f * v * (1.0f + erff(v * 0.70710678118654752440f));
}

__global__ __launch_bounds__(NTHREADS, 1) void gemm2_mma_kernel(const float* __restrict__ bias,
                                                                float* __restrict__ out) {
    extern __shared__ __align__(128) char smem[];
    const uint32_t sb = smem_u32(smem);
    const int tid = threadIdx.x, wid = tid >> 5, lane = tid & 31;
    const int mBase = blockIdx.y * 128;
    const int nBase = blockIdx.x * 256;

    float acc[4][8][4];
#pragma unroll
    for (int i = 0; i < 4; i++)
#pragma unroll
        for (int j = 0; j < 8; j++)
#pragma unroll
            for (int k = 0; k < 4; k++) acc[i][j][k] = 0.f;

    gemm_mainloop(sb, tid, wid, lane, acc,
                  g_g1 + (size_t)mBase * 512,
                  g_W + (size_t)nBase * 512);

    const int m0 = (wid & 1) * 64, n0 = (wid >> 1) * 64;
    const int g = lane >> 2, t = lane & 3;
#pragma unroll
    for (int mt = 0; mt < 4; mt++)
#pragma unroll
        for (int nt = 0; nt < 8; nt++) {
            const int r0 = mBase + m0 + mt * 16 + g;
            const int col = nBase + n0 + nt * 8 + t * 2;
            const float b0 = __ldg(bias + col), b1 = __ldg(bias + col + 1);
            float2 v0, v1;
            v0.x = gelu_exact(acc[mt][nt][0] + b0);
            v0.y = gelu_exact(acc[mt][nt][1] + b1);
            v1.x = gelu_exact(acc[mt][nt][2] + b0);
            v1.y = gelu_exact(acc[mt][nt][3] + b1);
            *(float2*)(out + (size_t)r0 * 512 + col) = v0;
            *(float2*)(out + (size_t)(r0 + 8) * 512 + col) = v1;
        }
}

// ---------------------------------------------------------------------------
// Quantum circuit + pre/post projections (one block per batch element)
// ---------------------------------------------------------------------------
__global__ void quantum_kernel(const float* __restrict__ pre_w,
                               const float* __restrict__ pre_b,
                               const float* __restrict__ post_w,
                               const float* __restrict__ post_b,
                               const float* __restrict__ qw,
                               float* __restrict__ out) {
    const int b = blockIdx.x;
    const int tid = threadIdx.x;
    const int warp = tid >> 5;
    const int lane = tid & 31;

    __shared__ float angles[NQ];
    __shared__ float sre[256], sim_[256];
    __shared__ float probs[256];
    __shared__ float zs[NQ];

    const float* tgt = out + (size_t)b * N_SZ * H_SZ;

    {
        float partial = 0.f;
        const float* pw = pre_w + warp * H_SZ;
        for (int k = lane; k < H_SZ; k += 32) partial += tgt[k] * pw[k];
#pragma unroll
        for (int o = 16; o; o >>= 1) partial += __shfl_down_sync(0xffffffffu, partial, o);
        if (lane == 0)
            angles[warp] = tanhf(partial + pre_b[warp]) * 3.14159265358979323846f;
    }

    sre[tid] = (tid == 0) ? 1.f : 0.f;
    sim_[tid] = 0.f;
    __syncthreads();

    for (int w = 0; w < NQ; w++) {
        const int mask = 1 << (7 - w);
        const float th = angles[w] * 0.5f;
        const float c = cosf(th), s = sinf(th);
        if (tid < 128) {
            const int i0 = ((tid & ~(mask - 1)) << 1) | (tid & (mask - 1));
            const int i1 = i0 | mask;
            float a0r = sre[i0], a0i = sim_[i0];
            float a1r = sre[i1], a1i = sim_[i1];
            sre[i0] = c * a0r - s * a1r;
            sim_[i0] = c * a0i - s * a1i;
            sre[i1] = s * a0r + c * a1r;
            sim_[i1] = s * a0i + c * a1i;
        }
        __syncthreads();
    }

    for (int l = 0; l < NLAYERS; l++) {
        for (int w = 0; w < NQ; w++) {
            const int mask = 1 << (7 - w);
            const float th = qw[l * NQ + w] * 0.5f;
            const float c = cosf(th), s = sinf(th);
            if (tid < 128) {
                const int i0 = ((tid & ~(mask - 1)) << 1) | (tid & (mask - 1));
                const int i1 = i0 | mask;
                float a0r = sre[i0], a0i = sim_[i0];
                float a1r = sre[i1], a1i = sim_[i1];
                sre[i0] = c * a0r + s * a1i;
                sim_[i0] = c * a0i - s * a1r;
                sre[i1] = c * a1r + s * a0i;
                sim_[i1] = c * a1i - s * a0r;
            }
            __syncthreads();
        }
        for (int w = 0; w < NQ; w++) {
            const int t = (w + 1) & 7;
            const int mc = 1 << (7 - w);
            const int mt = 1 << (7 - t);
            const int src = (tid & mc) ? (tid ^ mt) : tid;
            const float vr = sre[src], vi = sim_[src];
            __syncthreads();
            sre[tid] = vr;
            sim_[tid] = vi;
            __syncthreads();
        }
    }

    probs[tid] = sre[tid] * sre[tid] + sim_[tid] * sim_[tid];
    __syncthreads();
    {
        const int m = 1 << (7 - warp);
        float z = 0.f;
        for (int i = lane; i < 256; i += 32)
            z += (i & m) ? -probs[i] : probs[i];
#pragma unroll
        for (int o = 16; o; o >>= 1) z += __shfl_down_sync(0xffffffffu, z, o);
        if (lane == 0) zs[warp] = z;
    }
    __syncthreads();

    for (int h = tid; h < H_SZ; h += 256) {
        float acc = post_b[h];
#pragma unroll
        for (int q = 0; q < NQ; q++) acc += zs[q] * post_w[h * NQ + q];
        out[(size_t)b * N_SZ * H_SZ + h] = acc;
    }
}

// ---------------------------------------------------------------------------
extern "C" void kernel_launch(void* const* d_in, const int* in_sizes, int n_in,
                              void* d_out, int out_size) {
    const float* x      = (const float*)d_in[0];
    const float* adj    = (const float*)d_in[1];
    const float* Wg     = (const float*)d_in[2];
    const float* bg     = (const float*)d_in[3];
    const float* pre_w  = (const float*)d_in[4];
    const float* pre_b  = (const float*)d_in[5];
    const float* post_w = (const float*)d_in[6];
    const float* post_b = (const float*)d_in[7];
    const float* qw     = (const float*)d_in[8];
    float* out = (float*)d_out;

    cudaFuncSetAttribute(gemm1_mma_kernel,
                         cudaFuncAttributeMaxDynamicSharedMemorySize, SMEM_GEMM);
    cudaFuncSetAttribute(gemm2_mma_kernel,
                         cudaFuncAttributeMaxDynamicSharedMemorySize, SMEM_GEMM);

    conv_xT_kernel<<<dim3(16, 16, 64), 256>>>(x);
    conv_small_kernel<<<dim3(256, 2), 256>>>(adj, Wg);
    gemm1_mma_kernel<<<dim3(2, 4, 64), NTHREADS, SMEM_GEMM>>>();
    gemm2_mma_kernel<<<dim3(2, 256), NTHREADS, SMEM_GEMM>>>(bg, out);
    quantum_kernel<<<B_SZ, 256>>>(pre_w, pre_b, post_w, post_b, qw, out);
}

// round 15
// speedup vs baseline: 1.8136x; 1.2362x over previous
#include <cuda_runtime.h>
#include <cuda_fp16.h>
#include <cstdint>
#include <math.h>

#define B_SZ 64
#define N_SZ 512
#define H_SZ 512
#define NQ 8
#define NLAYERS 4

#define KCHUNK 64
#define TILE_BYTES 16384                // 16KB per operand tile
#define STAGE_BYTES (2 * TILE_BYTES)    // 32KB: A + B
#define NSTAGE 3
#define SMEM_GEMM (NSTAGE * STAGE_BYTES)   // 96KB -> 2 CTAs/SM
#define NTHREADS 256
#define NPERSIST 296                    // 2 x 148 SMs

// ---------------------------------------------------------------------------
// Static scratch (no allocs allowed)
// ---------------------------------------------------------------------------
__device__ __half g_x16[(size_t)B_SZ * N_SZ * H_SZ];  // rounded fp16, [b,j,h]
__device__ __half g_adj[N_SZ * N_SZ];                 // rounded fp16
__device__ __half g_W[H_SZ * H_SZ];                   // rounded fp16
__device__ __half g_g1[(size_t)B_SZ * N_SZ * H_SZ];   // fp16

// ---------------------------------------------------------------------------
// helpers
// ---------------------------------------------------------------------------
__device__ __forceinline__ uint32_t smem_u32(const void* p) {
    uint32_t a;
    asm("{ .reg .u64 t; cvta.to.shared.u64 t, %1; cvt.u32.u64 %0, t; }" : "=r"(a) : "l"(p));
    return a;
}
// SW128 swizzle (bits[6:4] ^= bits[9:7]) — for 128B rows
__device__ __forceinline__ uint32_t swz(uint32_t o) { return o ^ ((o >> 3) & 0x70); }

__device__ __forceinline__ void cp16(uint32_t dst, const void* src) {
    asm volatile("cp.async.cg.shared.global [%0], [%1], 16;" :: "r"(dst), "l"(src));
}
__device__ __forceinline__ void ldsm4(uint32_t* r, uint32_t addr) {
    asm volatile("ldmatrix.sync.aligned.m8n8.x4.shared.b16 {%0,%1,%2,%3}, [%4];"
                 : "=r"(r[0]), "=r"(r[1]), "=r"(r[2]), "=r"(r[3]) : "r"(addr));
}
__device__ __forceinline__ void ldsm4t(uint32_t* r, uint32_t addr) {
    asm volatile("ldmatrix.sync.aligned.m8n8.x4.trans.shared.b16 {%0,%1,%2,%3}, [%4];"
                 : "=r"(r[0]), "=r"(r[1]), "=r"(r[2]), "=r"(r[3]) : "r"(addr));
}
__device__ __forceinline__ void mma_f16(float* c, const uint32_t* a, const uint32_t* b) {
    asm volatile(
        "mma.sync.aligned.m16n8k16.row.col.f32.f16.f16.f32 "
        "{%0,%1,%2,%3}, {%4,%5,%6,%7}, {%8,%9}, {%0,%1,%2,%3};"
        : "+f"(c[0]), "+f"(c[1]), "+f"(c[2]), "+f"(c[3])
        : "r"(a[0]), "r"(a[1]), "r"(a[2]), "r"(a[3]), "r"(b[0]), "r"(b[1]));
}

// ---------------------------------------------------------------------------
// Conversion kernels
// ---------------------------------------------------------------------------
// x fp32 -> fp16, fully coalesced (no transpose). 8 elems/thread.
__global__ void conv_x_kernel(const float* __restrict__ x) {
    const size_t i = ((size_t)blockIdx.x * 256 + threadIdx.x) * 8;
    float4 v0 = *(const float4*)(x + i);
    float4 v1 = *(const float4*)(x + i + 4);
    __half2 h[4];
    h[0] = __floats2half2_rn(v0.x, v0.y);
    h[1] = __floats2half2_rn(v0.z, v0.w);
    h[2] = __floats2half2_rn(v1.x, v1.y);
    h[3] = __floats2half2_rn(v1.z, v1.w);
    *(uint4*)(g_x16 + i) = *(uint4*)h;
}

// adj and W -> single fp16 planes
__global__ void conv_small_kernel(const float* __restrict__ adj,
                                  const float* __restrict__ W) {
    int base = blockIdx.x * 1024 + threadIdx.x;
    const float* src = (blockIdx.y == 0) ? adj : W;
    __half* dst = (blockIdx.y == 0) ? g_adj : g_W;
#pragma unroll
    for (int i = 0; i < 4; i++) {
        int idx = base + i * 256;
        dst[idx] = __float2half(src[idx]);
    }
}

// ---------------------------------------------------------------------------
// GEMM plumbing.  CTA tile 128x128, 8 warps (2x4), warp tile 64x32.
// BT=false: B stored [n=128 rows][k 128B rows] (K-major, non-trans ldsm)
// BT=true : B stored [k=64 rows][n 256B rows] (natural x layout, trans ldsm)
// ---------------------------------------------------------------------------
template <bool BT>
__device__ __forceinline__ void prefetch_chunk(
    uint32_t sb, int stage, int kc, int tid,
    const __half* __restrict__ A, const __half* __restrict__ B) {
    const uint32_t base = sb + stage * STAGE_BYTES;
    const __half* As = A + kc * KCHUNK;
#pragma unroll
    for (int i = 0; i < 4; i++) {          // A: 1024 16B-chunks, 128B rows
        const int j = tid + i * NTHREADS;
        const int row = j >> 3, c = j & 7;
        cp16(base + swz(row * 128 + c * 16), As + (size_t)row * 512 + c * 8);
    }
    if (BT) {
        // B: 64 k-rows x 256B, row-local XOR swizzle
        const __half* Bs = B + (size_t)kc * KCHUNK * 512;
#pragma unroll
        for (int i = 0; i < 4; i++) {
            const int j = tid + i * NTHREADS;  // 0..1023
            const int row = j >> 4, c = j & 15;
            cp16(base + TILE_BYTES + row * 256 + ((c ^ (row & 7)) * 16),
                 Bs + (size_t)row * 512 + c * 8);
        }
    } else {
        const __half* Bs = B + kc * KCHUNK;
#pragma unroll
        for (int i = 0; i < 4; i++) {
            const int j = tid + i * NTHREADS;
            const int row = j >> 3, c = j & 7;
            cp16(base + TILE_BYTES + swz(row * 128 + c * 16),
                 Bs + (size_t)row * 512 + c * 8);
        }
    }
    asm volatile("cp.async.commit_group;");
}

// fp16 MMA over one 128x128x64 chunk. Warp computes 64x32.
template <bool BT>
__device__ __forceinline__ void compute_chunk(uint32_t sb, int stage, int wid, int lane,
                                              float acc[4][4][4]) {
    const uint32_t base = sb + stage * STAGE_BYTES;
    const int m0 = (wid & 1) * 64;
    const int n0 = (wid >> 1) * 32;
    const int ar = (lane & 7) + ((lane >> 3) & 1) * 8;
    const int ac = ((lane >> 4) & 1) * 8;
    // non-trans B addressing
    const int br = (lane & 7) + ((lane >> 4) & 1) * 8;
    const int bc = ((lane >> 3) & 1) * 8;
    // trans B addressing: matrix = lane>>3 -> k-half bit3, n-half bit4
    const int krow_lo = ((lane >> 3) & 1) * 8 + (lane & 7);
    const int nsel = ((lane >> 4) & 1) * 8;
#pragma unroll
    for (int ks = 0; ks < 4; ks++) {
        uint32_t a[4][4], b[4][2];
#pragma unroll
        for (int mt = 0; mt < 4; mt++) {
            const uint32_t off = swz((m0 + mt * 16 + ar) * 128 + (ks * 16 + ac) * 2);
            ldsm4(a[mt], base + off);
        }
#pragma unroll
        for (int nt2 = 0; nt2 < 2; nt2++) {
            uint32_t r[4];
            if (BT) {
                const int n_off = n0 + nt2 * 16 + nsel;
                const int krow = ks * 16 + krow_lo;
                const uint32_t off = krow * 256 + (((n_off >> 3) ^ (krow & 7)) * 16);
                ldsm4t(r, base + TILE_BYTES + off);
            } else {
                const uint32_t off = swz((n0 + nt2 * 16 + br) * 128 + (ks * 16 + bc) * 2);
                ldsm4(r, base + TILE_BYTES + off);
            }
            b[nt2 * 2][0] = r[0]; b[nt2 * 2][1] = r[1];
            b[nt2 * 2 + 1][0] = r[2]; b[nt2 * 2 + 1][1] = r[3];
        }
#pragma unroll
        for (int mt = 0; mt < 4; mt++)
#pragma unroll
            for (int nt = 0; nt < 4; nt++)
                mma_f16(acc[mt][nt], a[mt], b[nt]);
    }
}

// 8 chunks of K=64, 3-stage pipeline, ONE barrier per iteration.
template <bool BT>
__device__ __forceinline__ void gemm_mainloop(
    uint32_t sb, int tid, int wid, int lane, float acc[4][4][4],
    const __half* A, const __half* B) {
    prefetch_chunk<BT>(sb, 0, 0, tid, A, B);
    prefetch_chunk<BT>(sb, 1, 1, tid, A, B);
#pragma unroll 1
    for (int kc = 0; kc < 8; kc++) {
        if (kc == 7) asm volatile("cp.async.wait_group 0;");
        else         asm volatile("cp.async.wait_group 1;");
        __syncthreads();
        if (kc + 2 < 8)
            prefetch_chunk<BT>(sb, (kc + 2) % NSTAGE, kc + 2, tid, A, B);
        compute_chunk<BT>(sb, kc % NSTAGE, wid, lane, acc);
    }
}

// ---------------------------------------------------------------------------
// GEMM1 (persistent): g1[b,i,h] = sum_j adj[i,j]*x[b,j,h] -> fp16.
// 1024 tiles = (b:64) x (by:4) x (bx:4);  grid = NPERSIST.
// ---------------------------------------------------------------------------
__global__ __launch_bounds__(NTHREADS, 2) void gemm1_mma_kernel() {
    extern __shared__ __align__(128) char smem[];
    const uint32_t sb = smem_u32(smem);
    const int tid = threadIdx.x, wid = tid >> 5, lane = tid & 31;

#pragma unroll 1
    for (int tile = blockIdx.x; tile < 1024; tile += NPERSIST) {
        const int b = tile >> 4;
        const int iBase = ((tile >> 2) & 3) * 128;
        const int hBase = (tile & 3) * 128;

        float acc[4][4][4];
#pragma unroll
        for (int i = 0; i < 4; i++)
#pragma unroll
            for (int j = 0; j < 4; j++)
#pragma unroll
                for (int k = 0; k < 4; k++) acc[i][j][k] = 0.f;

        gemm_mainloop<true>(sb, tid, wid, lane, acc,
                            g_adj + (size_t)iBase * 512,
                            g_x16 + (size_t)b * 512 * 512 + hBase);

        const int m0 = (wid & 1) * 64, n0 = (wid >> 1) * 32;
        const int g = lane >> 2, t = lane & 3;
#pragma unroll
        for (int mt = 0; mt < 4; mt++)
#pragma unroll
            for (int nt = 0; nt < 4; nt++) {
                const int r0 = iBase + m0 + mt * 16 + g;
                const int col = hBase + n0 + nt * 8 + t * 2;
                const size_t o0 = ((size_t)b * 512 + r0) * 512 + col;
                const size_t o1 = o0 + (size_t)8 * 512;
                __half2 v0, v1;
                v0.x = __float2half(acc[mt][nt][0]);
                v0.y = __float2half(acc[mt][nt][1]);
                v1.x = __float2half(acc[mt][nt][2]);
                v1.y = __float2half(acc[mt][nt][3]);
                *(__half2*)(g_g1 + o0) = v0;
                *(__half2*)(g_g1 + o1) = v1;
            }
        __syncthreads();   // guard stage reuse across tiles
    }
}

// ---------------------------------------------------------------------------
// GEMM2 (persistent) + bias + exact GELU.  1024 tiles = (by:256) x (bx:4).
// ---------------------------------------------------------------------------
__device__ __forceinline__ float gelu_exact(float v) {
    return 0.5f * v * (1.0f + erff(v * 0.70710678118654752440f));
}

__global__ __launch_bounds__(NTHREADS, 2) void gemm2_mma_kernel(const float* __restrict__ bias,
                                                                float* __restrict__ out) {
    extern __shared__ __align__(128) char smem[];
    const uint32_t sb = smem_u32(smem);
    const int tid = threadIdx.x, wid = tid >> 5, lane = tid & 31;

#pragma unroll 1
    for (int tile = blockIdx.x; tile < 1024; tile += NPERSIST) {
        const int mBase = (tile >> 2) * 128;
        const int nBase = (tile & 3) * 128;

        float acc[4][4][4];
#pragma unroll
        for (int i = 0; i < 4; i++)
#pragma unroll
            for (int j = 0; j < 4; j++)
#pragma unroll
                for (int k = 0; k < 4; k++) acc[i][j][k] = 0.f;

        gemm_mainloop<false>(sb, tid, wid, lane, acc,
                             g_g1 + (size_t)mBase * 512,
                             g_W + (size_t)nBase * 512);

        const int m0 = (wid & 1) * 64, n0 = (wid >> 1) * 32;
        const int g = lane >> 2, t = lane & 3;
#pragma unroll
        for (int mt = 0; mt < 4; mt++)
#pragma unroll
            for (int nt = 0; nt < 4; nt++) {
                const int r0 = mBase + m0 + mt * 16 + g;
                const int col = nBase + n0 + nt * 8 + t * 2;
                const float b0 = __ldg(bias + col), b1 = __ldg(bias + col + 1);
                float2 v0, v1;
                v0.x = gelu_exact(acc[mt][nt][0] + b0);
                v0.y = gelu_exact(acc[mt][nt][1] + b1);
                v1.x = gelu_exact(acc[mt][nt][2] + b0);
                v1.y = gelu_exact(acc[mt][nt][3] + b1);
                *(float2*)(out + (size_t)r0 * 512 + col) = v0;
                *(float2*)(out + (size_t)(r0 + 8) * 512 + col) = v1;
            }
        __syncthreads();   // guard stage reuse across tiles
    }
}

// ---------------------------------------------------------------------------
// Quantum circuit + pre/post projections (one block per batch element)
// ---------------------------------------------------------------------------
__global__ void quantum_kernel(const float* __restrict__ pre_w,
                               const float* __restrict__ pre_b,
                               const float* __restrict__ post_w,
                               const float* __restrict__ post_b,
                               const float* __restrict__ qw,
                               float* __restrict__ out) {
    const int b = blockIdx.x;
    const int tid = threadIdx.x;
    const int warp = tid >> 5;
    const int lane = tid & 31;

    __shared__ float angles[NQ];
    __shared__ float sre[256], sim_[256];
    __shared__ float probs[256];
    __shared__ float zs[NQ];

    const float* tgt = out + (size_t)b * N_SZ * H_SZ;

    {
        float partial = 0.f;
        const float* pw = pre_w + warp * H_SZ;
        for (int k = lane; k < H_SZ; k += 32) partial += tgt[k] * pw[k];
#pragma unroll
        for (int o = 16; o; o >>= 1) partial += __shfl_down_sync(0xffffffffu, partial, o);
        if (lane == 0)
            angles[warp] = tanhf(partial + pre_b[warp]) * 3.14159265358979323846f;
    }

    sre[tid] = (tid == 0) ? 1.f : 0.f;
    sim_[tid] = 0.f;
    __syncthreads();

    for (int w = 0; w < NQ; w++) {
        const int mask = 1 << (7 - w);
        const float th = angles[w] * 0.5f;
        const float c = cosf(th), s = sinf(th);
        if (tid < 128) {
            const int i0 = ((tid & ~(mask - 1)) << 1) | (tid & (mask - 1));
            const int i1 = i0 | mask;
            float a0r = sre[i0], a0i = sim_[i0];
            float a1r = sre[i1], a1i = sim_[i1];
            sre[i0] = c * a0r - s * a1r;
            sim_[i0] = c * a0i - s * a1i;
            sre[i1] = s * a0r + c * a1r;
            sim_[i1] = s * a0i + c * a1i;
        }
        __syncthreads();
    }

    for (int l = 0; l < NLAYERS; l++) {
        for (int w = 0; w < NQ; w++) {
            const int mask = 1 << (7 - w);
            const float th = qw[l * NQ + w] * 0.5f;
            const float c = cosf(th), s = sinf(th);
            if (tid < 128) {
                const int i0 = ((tid & ~(mask - 1)) << 1) | (tid & (mask - 1));
                const int i1 = i0 | mask;
                float a0r = sre[i0], a0i = sim_[i0];
                float a1r = sre[i1], a1i = sim_[i1];
                sre[i0] = c * a0r + s * a1i;
                sim_[i0] = c * a0i - s * a1r;
                sre[i1] = c * a1r + s * a0i;
                sim_[i1] = c * a1i - s * a0r;
            }
            __syncthreads();
        }
        for (int w = 0; w < NQ; w++) {
            const int t = (w + 1) & 7;
            const int mc = 1 << (7 - w);
            const int mt = 1 << (7 - t);
            const int src = (tid & mc) ? (tid ^ mt) : tid;
            const float vr = sre[src], vi = sim_[src];
            __syncthreads();
            sre[tid] = vr;
            sim_[tid] = vi;
            __syncthreads();
        }
    }

    probs[tid] = sre[tid] * sre[tid] + sim_[tid] * sim_[tid];
    __syncthreads();
    {
        const int m = 1 << (7 - warp);
        float z = 0.f;
        for (int i = lane; i < 256; i += 32)
            z += (i & m) ? -probs[i] : probs[i];
#pragma unroll
        for (int o = 16; o; o >>= 1) z += __shfl_down_sync(0xffffffffu, z, o);
        if (lane == 0) zs[warp] = z;
    }
    __syncthreads();

    for (int h = tid; h < H_SZ; h += 256) {
        float acc = post_b[h];
#pragma unroll
        for (int q = 0; q < NQ; q++) acc += zs[q] * post_w[h * NQ + q];
        out[(size_t)b * N_SZ * H_SZ + h] = acc;
    }
}

// ---------------------------------------------------------------------------
extern "C" void kernel_launch(void* const* d_in, const int* in_sizes, int n_in,
                              void* d_out, int out_size) {
    const float* x      = (const float*)d_in[0];
    const float* adj    = (const float*)d_in[1];
    const float* Wg     = (const float*)d_in[2];
    const float* bg     = (const float*)d_in[3];
    const float* pre_w  = (const float*)d_in[4];
    const float* pre_b  = (const float*)d_in[5];
    const float* post_w = (const float*)d_in[6];
    const float* post_b = (const float*)d_in[7];
    const float* qw     = (const float*)d_in[8];
    float* out = (float*)d_out;

    cudaFuncSetAttribute(gemm1_mma_kernel,
                         cudaFuncAttributeMaxDynamicSharedMemorySize, SMEM_GEMM);
    cudaFuncSetAttribute(gemm2_mma_kernel,
                         cudaFuncAttributeMaxDynamicSharedMemorySize, SMEM_GEMM);

    conv_x_kernel<<<(B_SZ * N_SZ * H_SZ) / (256 * 8), 256>>>(x);
    conv_small_kernel<<<dim3(256, 2), 256>>>(adj, Wg);
    gemm1_mma_kernel<<<NPERSIST, NTHREADS, SMEM_GEMM>>>();
    gemm2_mma_kernel<<<NPERSIST, NTHREADS, SMEM_GEMM>>>(bg, out);
    quantum_kernel<<<B_SZ, 256>>>(pre_w, pre_b, post_w, post_b, qw, out);
}